// round 2
// baseline (speedup 1.0000x reference)
#include <cuda_runtime.h>
#include <cuda_bf16.h>
#include <cstdint>

// Problem constants
#define BATCH   2
#define CIN     256
#define OC_QKV  384
#define NP      65536      // d*h*w = 16*64*64 spatial positions per batch
#define HEADS   4
#define DH      32
#define SCALE_Q 0.17677669529663687f   // 32^-0.5

// ---------------------------------------------------------------------------
// Scratch (device globals; no allocation allowed anywhere)
// ---------------------------------------------------------------------------
__device__ float g_qkv[(size_t)BATCH * OC_QKV * NP];   // [b][384][p]  (201 MB)
__device__ float g_out[(size_t)BATCH * 128 * NP];      // [b][128][p]  (67 MB)
__device__ float g_rowmax[BATCH * 128];
__device__ float g_rowsum[BATCH * 128];
__device__ float g_ctx[BATCH * HEADS * DH * DH];       // [b][h][d][e]

// ---------------------------------------------------------------------------
// GEMM body:  Y[b][m][p] = sum_k W[m][k] * X[b][k][p]  (+ bias[m])
// BM=128, BN=128, BK=16, 256 threads, 8o x 8p per thread.
// Inner product uses packed fma.rn.f32x2 (FFMA2) — 2 fp32 lanes per issue.
// M % 128 == 0, K % 16 == 0, N % 128 == 0 (holds for both call sites).
// ---------------------------------------------------------------------------
__device__ __forceinline__ void gemm_body(
    const float* __restrict__ W, const float* __restrict__ X,
    float* __restrict__ Y, const float* __restrict__ bias,
    int M, int K, int N_)
{
    __shared__ float Ws[16][132];   // transposed: Ws[k][o], pad keeps 16B align
    __shared__ float Xs[16][132];   // Xs[k][p]

    const int b   = blockIdx.z;
    const float* Xb = X + (size_t)b * K * N_;
    float*       Yb = Y + (size_t)b * M * N_;
    const int m0  = blockIdx.y * 128;
    const int n0  = blockIdx.x * 128;
    const int tid = threadIdx.x;
    const int og  = tid >> 4;   // 0..15 -> o = m0 + og*8 + {0..7}
    const int pg  = tid & 15;   // 0..15 -> p = n0 + pg + j*16

    unsigned long long acc[4][8];   // o-pairs (o,o+1) x 8 p, packed f32x2
#pragma unroll
    for (int i = 0; i < 4; i++)
#pragma unroll
        for (int j = 0; j < 8; j++) acc[i][j] = 0ull;

    for (int k0 = 0; k0 < K; k0 += 16) {
        // --- load W tile (128 x 16) transposed into Ws[k][o]
#pragma unroll
        for (int i = 0; i < 2; i++) {
            int idx = i * 256 + tid;
            int row = idx >> 2;
            int c4  = (idx & 3) * 4;
            float4 w4 = *(const float4*)(W + (size_t)(m0 + row) * K + k0 + c4);
            Ws[c4 + 0][row] = w4.x;
            Ws[c4 + 1][row] = w4.y;
            Ws[c4 + 2][row] = w4.z;
            Ws[c4 + 3][row] = w4.w;
        }
        // --- load X tile (16 x 128)
#pragma unroll
        for (int i = 0; i < 2; i++) {
            int idx = i * 256 + tid;
            int row = idx >> 5;
            int c4  = (idx & 31) * 4;
            *(float4*)&Xs[row][c4] =
                *(const float4*)(Xb + (size_t)(k0 + row) * N_ + n0 + c4);
        }
        __syncthreads();

#pragma unroll
        for (int k = 0; k < 16; k++) {
            unsigned long long a[4];
#pragma unroll
            for (int i = 0; i < 4; i++)
                a[i] = *(const unsigned long long*)&Ws[k][og * 8 + i * 2];
#pragma unroll
            for (int j = 0; j < 8; j++) {
                float bv = Xs[k][pg + j * 16];
                unsigned long long bb;
                asm("mov.b64 %0, {%1, %1};" : "=l"(bb) : "r"(__float_as_uint(bv)));
#pragma unroll
                for (int i = 0; i < 4; i++)
                    asm("fma.rn.f32x2 %0, %1, %2, %0;"
                        : "+l"(acc[i][j]) : "l"(a[i]), "l"(bb));
            }
        }
        __syncthreads();
    }

    // --- epilogue
#pragma unroll
    for (int i = 0; i < 4; i++) {
        int o0 = m0 + og * 8 + i * 2;
        float bias0 = bias ? bias[o0]     : 0.f;
        float bias1 = bias ? bias[o0 + 1] : 0.f;
#pragma unroll
        for (int j = 0; j < 8; j++) {
            unsigned lo, hi;
            asm("mov.b64 {%0, %1}, %2;" : "=r"(lo), "=r"(hi) : "l"(acc[i][j]));
            int p = n0 + pg + j * 16;
            Yb[(size_t)o0 * N_ + p]       = __uint_as_float(lo) + bias0;
            Yb[(size_t)(o0 + 1) * N_ + p] = __uint_as_float(hi) + bias1;
        }
    }
}

// Wrapper 1: qkv = Wqkv @ x   (destination is the device-global scratch)
__global__ void __launch_bounds__(256)
gemm_qkv_kernel(const float* __restrict__ W, const float* __restrict__ X)
{
    gemm_body(W, X, g_qkv, nullptr, OC_QKV, CIN, NP);
}

// Wrapper 2: y = Wout @ g_out + b_out   (source is the device-global scratch)
__global__ void __launch_bounds__(256)
gemm_out_kernel(const float* __restrict__ W, float* __restrict__ Y,
                const float* __restrict__ bias)
{
    gemm_body(W, g_out, Y, bias, 256, 128, NP);
}

// ---------------------------------------------------------------------------
// Row-max over each of the 256 k-rows (length 65536). Block 0 additionally
// zeroes the context / rowsum accumulators (fresh on every graph replay).
// ---------------------------------------------------------------------------
__global__ void __launch_bounds__(256)
rowmax_kernel()
{
    const int r   = blockIdx.x;          // 0..255
    const int b   = r >> 7;
    const int row = r & 127;
    const int tid = threadIdx.x;

    if (blockIdx.x == 0) {
        for (int i = tid; i < BATCH * HEADS * DH * DH; i += 256) g_ctx[i] = 0.f;
        if (tid < BATCH * 128) g_rowsum[tid] = 0.f;
    }

    const float4* k4 =
        (const float4*)(g_qkv + ((size_t)b * OC_QKV + 128 + row) * NP);
    float m = -3.402823466e38f;
    for (int i = tid; i < NP / 4; i += 256) {
        float4 v = k4[i];
        m = fmaxf(m, fmaxf(fmaxf(v.x, v.y), fmaxf(v.z, v.w)));
    }
    __shared__ float red[256];
    red[tid] = m;
    __syncthreads();
    for (int s = 128; s > 0; s >>= 1) {
        if (tid < s) red[tid] = fmaxf(red[tid], red[tid + s]);
        __syncthreads();
    }
    if (tid == 0) g_rowmax[r] = red[0];
}

// ---------------------------------------------------------------------------
// Per-(b,h): rowsum of exp(k - max) and context[d][e] = sum_p ek[d,p]*v[e,p].
// Each CTA handles a 2048-position chunk; partials via atomicAdd.
// ---------------------------------------------------------------------------
#define CTX_CHUNK 2048
__global__ void __launch_bounds__(256)
ctx_kernel()
{
    const int bh = blockIdx.y;           // 0..7
    const int b  = bh >> 2;
    const int h  = bh & 3;
    const int p0 = blockIdx.x * CTX_CHUNK;
    const int tid = threadIdx.x;

    __shared__ float ek[32][133];
    __shared__ float vs[32][133];
    __shared__ float rm[32];

    const float* kbase = g_qkv + ((size_t)b * OC_QKV + 128 + h * DH) * NP;
    const float* vbase = g_qkv + ((size_t)b * OC_QKV + 256 + h * DH) * NP;

    if (tid < 32) rm[tid] = g_rowmax[b * 128 + h * DH + tid];
    __syncthreads();

    const int d  = tid & 31;
    const int eg = tid >> 5;     // 0..7
    const int e0 = eg * 4;

    float acc0 = 0.f, acc1 = 0.f, acc2 = 0.f, acc3 = 0.f, srow = 0.f;

    for (int t = 0; t < CTX_CHUNK / 128; t++) {
        const int pt = p0 + t * 128;
        if (t) __syncthreads();
        // load 32x128 tiles: 1024 float4, 4 per thread
#pragma unroll
        for (int i = 0; i < 4; i++) {
            int idx = i * 256 + tid;
            int row = idx >> 5;
            int c4  = (idx & 31) * 4;
            float4 kv = *(const float4*)(kbase + (size_t)row * NP + pt + c4);
            float  mr = rm[row];
            ek[row][c4 + 0] = __expf(kv.x - mr);
            ek[row][c4 + 1] = __expf(kv.y - mr);
            ek[row][c4 + 2] = __expf(kv.z - mr);
            ek[row][c4 + 3] = __expf(kv.w - mr);
            float4 vv = *(const float4*)(vbase + (size_t)row * NP + pt + c4);
            vs[row][c4 + 0] = vv.x;
            vs[row][c4 + 1] = vv.y;
            vs[row][c4 + 2] = vv.z;
            vs[row][c4 + 3] = vv.w;
        }
        __syncthreads();
#pragma unroll 4
        for (int p = 0; p < 128; p++) {
            float ekv = ek[d][p];
            if (eg == 0) srow += ekv;      // warp-uniform branch
            acc0 += ekv * vs[e0 + 0][p];
            acc1 += ekv * vs[e0 + 1][p];
            acc2 += ekv * vs[e0 + 2][p];
            acc3 += ekv * vs[e0 + 3][p];
        }
    }

    float* ctx = g_ctx + (((size_t)b * HEADS + h) * DH + d) * DH;
    atomicAdd(&ctx[e0 + 0], acc0);
    atomicAdd(&ctx[e0 + 1], acc1);
    atomicAdd(&ctx[e0 + 2], acc2);
    atomicAdd(&ctx[e0 + 3], acc3);
    if (eg == 0) atomicAdd(&g_rowsum[b * 128 + h * DH + d], srow);
}

// ---------------------------------------------------------------------------
// out[b][h*32+e][p] = sum_d (ctx[b][h][d][e] * SCALE_Q / rowsum[d]) * q[d][p]
// One thread per spatial position.
// ---------------------------------------------------------------------------
__global__ void __launch_bounds__(256)
outk_kernel()
{
    const int b   = blockIdx.y;
    const int tid = threadIdx.x;
    const int p   = blockIdx.x * 256 + tid;

    __shared__ float ctxs[HEADS][DH][DH];
    for (int i = tid; i < HEADS * DH * DH; i += 256) {
        int h = i >> 10, d = (i >> 5) & 31, e = i & 31;
        ctxs[h][d][e] = g_ctx[(((size_t)b * HEADS + h) * DH + d) * DH + e] *
                        SCALE_Q / g_rowsum[b * 128 + h * DH + d];
    }
    __syncthreads();

    const float* qb = g_qkv + (size_t)b * OC_QKV * NP;
    float*       ob = g_out + (size_t)b * 128 * NP;

#pragma unroll
    for (int h = 0; h < HEADS; h++) {
        float qr[DH];
#pragma unroll
        for (int d = 0; d < DH; d++)
            qr[d] = qb[(size_t)(h * DH + d) * NP + p];
#pragma unroll
        for (int e = 0; e < DH; e++) {
            float s = 0.f;
#pragma unroll
            for (int d = 0; d < DH; d++) s += ctxs[h][d][e] * qr[d];
            ob[(size_t)(h * DH + e) * NP + p] = s;
        }
    }
}

// ---------------------------------------------------------------------------
// kernel_launch — pure kernel launches, nothing else (graph-capture safe)
// ---------------------------------------------------------------------------
extern "C" void kernel_launch(void* const* d_in, const int* in_sizes, int n_in,
                              void* d_out, int out_size)
{
    const float* x     = (const float*)d_in[0];
    const float* Wqkv  = (const float*)d_in[1];
    const float* Wout  = (const float*)d_in[2];
    const float* b_out = (const float*)d_in[3];
    float*       y     = (float*)d_out;

    // 1) qkv = Wqkv @ x
    gemm_qkv_kernel<<<dim3(NP / 128, OC_QKV / 128, BATCH), 256>>>(Wqkv, x);
    // 2) row maxes of k (+ zero accumulators)
    rowmax_kernel<<<256, 256>>>();
    // 3) softmax denominators + context matrices
    ctx_kernel<<<dim3(NP / CTX_CHUNK, BATCH * HEADS), 256>>>();
    // 4) out = (ctx/Z * scale)^T applied to q
    outk_kernel<<<dim3(NP / 256, BATCH), 256>>>();
    // 5) y = Wout @ out + b_out
    gemm_out_kernel<<<dim3(NP / 128, 256 / 128, BATCH), 256>>>(Wout, y, b_out);
}